// round 12
// baseline (speedup 1.0000x reference)
#include <cuda_runtime.h>
#include <cuda_fp16.h>
#include <stdint.h>

#define DI __device__ __forceinline__

// ---------------- problem constants ----------------
#define Bn 8192
#define In 512
#define Fn 64
#define On 512

#define MT 128
#define NT 256
#define STG 4
#define NTHR 384          // 8 consumer warps + 4 producer warps

// smem ring: A stages 4 x 16KB, B stages 4 x 32KB
#define A_BY 16384u
#define B_BY 32768u
#define SM_B0 (STG * A_BY)
#define SMEM_TOTAL (STG * (A_BY + B_BY))   // 196608

// ---------------- device scratch ----------------
__device__ __half g_Wmat[(size_t)In * On * Fn];  // [i][o][f]
__device__ float  g_af[Fn];
__device__ float  g_cf[Fn];
__device__ float  g_corr[On];

// ---------------- ptx helpers ----------------
DI uint32_t smem_u32(const void* p) {
    uint32_t a;
    asm("{ .reg .u64 t; cvta.to.shared.u64 t, %1; cvt.u32.u64 %0, t; }" : "=r"(a) : "l"(p));
    return a;
}
DI void cp_async16(uint32_t dst, const void* src) {
    size_t g = __cvta_generic_to_global(src);
    asm volatile("cp.async.cg.shared.global [%0], [%1], 16;" :: "r"(dst), "l"(g) : "memory");
}
DI void sts128(uint32_t addr, uint32_t r0, uint32_t r1, uint32_t r2, uint32_t r3) {
    asm volatile("st.shared.v4.b32 [%0], {%1,%2,%3,%4};"
                 :: "r"(addr), "r"(r0), "r"(r1), "r"(r2), "r"(r3) : "memory");
}
DI void ldsm4(uint32_t* r, uint32_t addr) {
    asm volatile("ldmatrix.sync.aligned.m8n8.x4.shared.b16 {%0,%1,%2,%3}, [%4];"
                 : "=r"(r[0]), "=r"(r[1]), "=r"(r[2]), "=r"(r[3]) : "r"(addr));
}
DI void mma16816(float* c, const uint32_t* a, const uint32_t* b) {
    asm volatile(
        "mma.sync.aligned.m16n8k16.row.col.f32.f16.f16.f32 "
        "{%0,%1,%2,%3}, {%4,%5,%6,%7}, {%8,%9}, {%0,%1,%2,%3};"
        : "+f"(c[0]), "+f"(c[1]), "+f"(c[2]), "+f"(c[3])
        : "r"(a[0]), "r"(a[1]), "r"(a[2]), "r"(a[3]), "r"(b[0]), "r"(b[1]));
}
DI void bar_sync(int id, int cnt) {
    asm volatile("bar.sync %0, %1;" :: "r"(id), "r"(cnt) : "memory");
}
DI void bar_arrive(int id, int cnt) {
    asm volatile("bar.arrive %0, %1;" :: "r"(id), "r"(cnt) : "memory");
}

// ---------------- prep kernels ----------------
__global__ void k_fconst(const float* __restrict__ freqs, const float* __restrict__ phases) {
    int f = threadIdx.x;
    if (f < Fn) {
        float w = freqs[f], p = phases[f];
        float m = expf(-0.5f * w * w) * sinf(p);
        float v = 0.5f - 0.5f * expf(-2.0f * w * w) * cosf(2.0f * p) - m * m;
        float a = rsqrtf(1e-3f + v);
        g_af[f] = a;
        g_cf[f] = m * a;
    }
}

__global__ void k_corr(const float* __restrict__ beta, const float* __restrict__ lamb,
                       const float* __restrict__ bias) {
    int o = blockIdx.x * blockDim.x + threadIdx.x;
    if (o < On) {
        float s1 = 0.f;
        for (int f = 0; f < Fn; ++f) s1 += g_cf[f] * beta[f * On + o];
        float s2 = 0.f;
        for (int i = 0; i < In; ++i) s2 += lamb[i * On + o];
        g_corr[o] = bias[o] - s1 * s2;
    }
}

__global__ void k_W(const float* __restrict__ beta, const float* __restrict__ lamb) {
    const int i = blockIdx.x;
    __half* dst = g_Wmat + (size_t)i * (On * Fn);
    for (int j = threadIdx.x; j < On * Fn; j += blockDim.x) {
        int o = j >> 6, f = j & 63;
        dst[j] = __float2half(lamb[i * On + o] * beta[f * On + o] * g_af[f]);
    }
}

// ---------------- main: warp-specialized fused sin + HMMA GEMM ----------------
// 8 consumer warps (wid 0-7): 64x64 warp tiles over CTA 128x256, MMA only.
// 4 producer warps (wid 8-11): sins (A) + cp.async (B) into 4-stage ring.
// Per-stage named barriers: full = id s (0..3), empty = id 4+s; count = 384.
__global__ void __launch_bounds__(NTHR, 1)
k_main(const float* __restrict__ x, const float* __restrict__ freqs,
       const float* __restrict__ phases, float* __restrict__ out) {
    extern __shared__ char smem[];
    const uint32_t sbase = smem_u32(smem);
    const int tid = threadIdx.x;
    const int lane = tid & 31;
    const int wid = tid >> 5;
    const int m0 = blockIdx.x * MT;
    const int n0 = blockIdx.y * NT;

    if (wid >= 8) {
        // ================= PRODUCER (128 threads) =================
        const int ptid = tid - 256;
        const int fg = ptid & 7;        // freq group: 8 freqs
        const int rg = ptid >> 3;       // 0..15 -> 8 rows each
        float wv[8], pv[8];
#pragma unroll
        for (int j = 0; j < 8; ++j) { wv[j] = freqs[fg * 8 + j]; pv[j] = phases[fg * 8 + j]; }
        const float* xp = x + (size_t)(m0 + rg * 8) * In;

        uint32_t a_off[8];
#pragma unroll
        for (int r = 0; r < 8; ++r) {
            uint32_t row = (uint32_t)(rg * 8 + r);
            a_off[r] = row * 128u + ((uint32_t)(fg * 16) ^ ((row & 7u) << 4));
        }

        // W: 2 rows (256B) per thread, 16 cp.async16
        const int wr0 = ptid * 2;
        uint32_t w_off[16];
#pragma unroll
        for (int q = 0; q < 16; ++q) {
            uint32_t row = (uint32_t)(wr0 + (q >> 3));
            w_off[q] = row * 128u + (((uint32_t)((q & 7) * 16)) ^ ((row & 7u) << 4));
        }

#pragma unroll 1
        for (int j = 0; j < In; ++j) {
            const int s = j & (STG - 1);
            if (j >= STG) bar_sync(4 + s, NTHR);   // wait stage empty

            // B tile via cp.async
            const uint32_t bb = sbase + SM_B0 + (uint32_t)s * B_BY;
            const __half* ws = g_Wmat + (size_t)j * (On * Fn) + (size_t)(n0 + wr0) * Fn;
#pragma unroll
            for (int q = 0; q < 16; ++q)
                cp_async16(bb + w_off[q], ws + (q >> 3) * Fn + (q & 7) * 8);
            asm volatile("cp.async.commit_group;" ::: "memory");

            // A tile: sins (8 rows x 8 freqs), overlaps cp.async flight
            const uint32_t ab = sbase + (uint32_t)s * A_BY;
#pragma unroll
            for (int r = 0; r < 8; ++r) {
                const float xv = __ldg(xp + (size_t)r * In + j);
                uint32_t h[4];
#pragma unroll
                for (int q = 0; q < 4; ++q) {
                    float s0 = __sinf(fmaf(wv[2 * q],     xv, pv[2 * q]));
                    float s1 = __sinf(fmaf(wv[2 * q + 1], xv, pv[2 * q + 1]));
                    __half2 hh = __floats2half2_rn(s0, s1);
                    h[q] = *reinterpret_cast<uint32_t*>(&hh);
                }
                sts128(ab + a_off[r], h[0], h[1], h[2], h[3]);
            }

            asm volatile("cp.async.wait_group 0;" ::: "memory");
            bar_arrive(s, NTHR);                   // publish stage full
        }
    } else {
        // ================= CONSUMER (256 threads, 8 warps) =================
        const int wm = wid & 1;        // 0..1 (M)
        const int wn = wid >> 1;       // 0..3 (N)
        const int sub = lane >> 3, l7 = lane & 7;
        const uint32_t lxor = (uint32_t)l7 << 4;
        const uint32_t aR = (uint32_t)(wm * 64 + (sub & 1) * 8 + l7);
        const uint32_t aH = (uint32_t)((sub >> 1) * 16);
        const uint32_t bR = (uint32_t)(wn * 64 + (sub >> 1) * 8 + l7);
        const uint32_t bH = (uint32_t)((sub & 1) * 16);

        float c[4][8][4];
#pragma unroll
        for (int mt = 0; mt < 4; ++mt)
#pragma unroll
            for (int nt = 0; nt < 8; ++nt)
#pragma unroll
                for (int q = 0; q < 4; ++q) c[mt][nt][q] = 0.f;

#pragma unroll 1
        for (int j = 0; j < In; ++j) {
            const int s = j & (STG - 1);
            bar_sync(s, NTHR);                     // wait stage full

            const uint32_t Ab = sbase + (uint32_t)s * A_BY + aR * 128u;
            const uint32_t Bb = sbase + SM_B0 + (uint32_t)s * B_BY + bR * 128u;
#pragma unroll
            for (int ks = 0; ks < 4; ++ks) {
                const uint32_t kc = (uint32_t)(ks * 32);
                uint32_t a[4][4];
#pragma unroll
                for (int mt = 0; mt < 4; ++mt)
                    ldsm4(a[mt], Ab + (uint32_t)(mt * 16 * 128) + ((kc + aH) ^ lxor));
                uint32_t b[4][4];
#pragma unroll
                for (int np = 0; np < 4; ++np)
                    ldsm4(b[np], Bb + (uint32_t)(np * 16 * 128) + ((kc + bH) ^ lxor));
#pragma unroll
                for (int mt = 0; mt < 4; ++mt)
#pragma unroll
                    for (int np = 0; np < 4; ++np) {
                        mma16816(c[mt][2 * np],     a[mt], &b[np][0]);
                        mma16816(c[mt][2 * np + 1], a[mt], &b[np][2]);
                    }
            }

            if (j < In - STG) bar_arrive(4 + s, NTHR);   // release stage
        }

        // ---- epilogue ----
        const int g = lane >> 2, t2 = lane & 3;
#pragma unroll
        for (int mt = 0; mt < 4; ++mt) {
#pragma unroll
            for (int nt = 0; nt < 8; ++nt) {
                const int row = m0 + wm * 64 + mt * 16 + g;
                const int col = n0 + wn * 64 + nt * 8 + t2 * 2;
                const float cr0 = g_corr[col], cr1 = g_corr[col + 1];
                float2 v0 = make_float2(c[mt][nt][0] + cr0, c[mt][nt][1] + cr1);
                float2 v1 = make_float2(c[mt][nt][2] + cr0, c[mt][nt][3] + cr1);
                *reinterpret_cast<float2*>(out + (size_t)row * On + col) = v0;
                *reinterpret_cast<float2*>(out + (size_t)(row + 8) * On + col) = v1;
            }
        }
    }
}

// ---------------- harness entry ----------------
extern "C" void kernel_launch(void* const* d_in, const int* in_sizes, int n_in,
                              void* d_out, int out_size) {
    (void)in_sizes; (void)n_in; (void)out_size;
    const float* x      = (const float*)d_in[0];
    const float* freqs  = (const float*)d_in[1];
    const float* phases = (const float*)d_in[2];
    const float* beta   = (const float*)d_in[3];
    const float* lamb   = (const float*)d_in[4];
    const float* bias   = (const float*)d_in[5];
    float* out = (float*)d_out;

    cudaFuncSetAttribute(k_main, cudaFuncAttributeMaxDynamicSharedMemorySize, SMEM_TOTAL);

    k_fconst<<<1, 64>>>(freqs, phases);
    k_corr<<<1, 512>>>(beta, lamb, bias);
    k_W<<<512, 256>>>(beta, lamb);
    k_main<<<dim3(Bn / MT, On / NT), NTHR, SMEM_TOTAL>>>(x, freqs, phases, out);
}

// round 16
// speedup vs baseline: 1.8861x; 1.8861x over previous
#include <cuda_runtime.h>
#include <cuda_fp16.h>
#include <stdint.h>

#define DI __device__ __forceinline__

// ---------------- problem constants ----------------
#define Bn 8192
#define In 512
#define Fn 64
#define On 512

#define MT 128
#define NT 256
#define STG 4

// smem: A stages 4 x (128 rows x 128B), B stages 4 x (256 rows x 128B)
#define A_BY 16384u
#define B_BY 32768u
#define SM_B0 (STG * A_BY)
#define SMEM_TOTAL (STG * (A_BY + B_BY))   // 196608

// ---------------- device scratch (static; no runtime alloc) ----------------
// W layout: [i][o][f] so each K-chunk i is a contiguous block of 512 rows x 128B
__device__ __half g_Wmat[(size_t)In * On * Fn];
__device__ float  g_af[Fn];
__device__ float  g_cf[Fn];
__device__ float  g_corr[On];

// ---------------- ptx helpers ----------------
DI uint32_t smem_u32(const void* p) {
    uint32_t a;
    asm("{ .reg .u64 t; cvta.to.shared.u64 t, %1; cvt.u32.u64 %0, t; }" : "=r"(a) : "l"(p));
    return a;
}
DI void cp_async16(uint32_t dst, const void* src) {
    size_t g = __cvta_generic_to_global(src);
    asm volatile("cp.async.cg.shared.global [%0], [%1], 16;" :: "r"(dst), "l"(g) : "memory");
}
DI void sts128(uint32_t addr, uint32_t r0, uint32_t r1, uint32_t r2, uint32_t r3) {
    asm volatile("st.shared.v4.b32 [%0], {%1,%2,%3,%4};"
                 :: "r"(addr), "r"(r0), "r"(r1), "r"(r2), "r"(r3) : "memory");
}
DI void ldsm4(uint32_t* r, uint32_t addr) {
    asm volatile("ldmatrix.sync.aligned.m8n8.x4.shared.b16 {%0,%1,%2,%3}, [%4];"
                 : "=r"(r[0]), "=r"(r[1]), "=r"(r[2]), "=r"(r[3]) : "r"(addr));
}
DI void mma16816(float* c, const uint32_t* a, const uint32_t* b) {
    asm volatile(
        "mma.sync.aligned.m16n8k16.row.col.f32.f16.f16.f32 "
        "{%0,%1,%2,%3}, {%4,%5,%6,%7}, {%8,%9}, {%0,%1,%2,%3};"
        : "+f"(c[0]), "+f"(c[1]), "+f"(c[2]), "+f"(c[3])
        : "r"(a[0]), "r"(a[1]), "r"(a[2]), "r"(a[3]), "r"(b[0]), "r"(b[1]));
}

// ---------------- prep kernels ----------------
__global__ void k_fconst(const float* __restrict__ freqs, const float* __restrict__ phases) {
    int f = threadIdx.x;
    if (f < Fn) {
        float w = freqs[f], p = phases[f];
        float m = expf(-0.5f * w * w) * sinf(p);
        float v = 0.5f - 0.5f * expf(-2.0f * w * w) * cosf(2.0f * p) - m * m;
        float a = rsqrtf(1e-3f + v);
        g_af[f] = a;
        g_cf[f] = m * a;
    }
}

__global__ void k_corr(const float* __restrict__ beta, const float* __restrict__ lamb,
                       const float* __restrict__ bias) {
    int o = blockIdx.x * blockDim.x + threadIdx.x;
    if (o < On) {
        float s1 = 0.f;
        for (int f = 0; f < Fn; ++f) s1 += g_cf[f] * beta[f * On + o];
        float s2 = 0.f;
        for (int i = 0; i < In; ++i) s2 += lamb[i * On + o];
        g_corr[o] = bias[o] - s1 * s2;
    }
}

// block = i (0..511); writes contiguous block W[i][o][f] = lamb[i,o]*beta[f,o]*af[f]
__global__ void k_W(const float* __restrict__ beta, const float* __restrict__ lamb) {
    const int i = blockIdx.x;
    __half* dst = g_Wmat + (size_t)i * (On * Fn);
    for (int j = threadIdx.x; j < On * Fn; j += blockDim.x) {
        int o = j >> 6, f = j & 63;
        dst[j] = __float2half(lamb[i * On + o] * beta[f * On + o] * g_af[f]);
    }
}

// ---------------- main fused sin + HMMA GEMM ----------------
// CTA 128x256, 16 warps, warp tile 64x32 (2 M-warps x 8 N-warps), 4-stage
// pipeline, TWO K-chunks per barrier; produce/consume order staggered by warp
// parity so the tensor pipe stays fed during produce phases.
__global__ void __launch_bounds__(512, 1)
k_main(const float* __restrict__ x, const float* __restrict__ freqs,
       const float* __restrict__ phases, float* __restrict__ out) {
    extern __shared__ char smem[];
    const uint32_t sbase = smem_u32(smem);
    const int tid = threadIdx.x;
    const int lane = tid & 31;
    const int wid = tid >> 5;
    const int wm = wid & 1;        // 0..1  (M)
    const int wn = wid >> 1;       // 0..7  (N)
    const int m0 = blockIdx.x * MT;
    const int n0 = blockIdx.y * NT;

    // ---- producer mapping: sins — fg = freq-group (8 freqs), rg covers 2 rows
    const int fg = tid & 7;
    const int rg = tid >> 3;       // 0..63
    float wv[8], pv[8];
#pragma unroll
    for (int j = 0; j < 8; ++j) { wv[j] = freqs[fg * 8 + j]; pv[j] = phases[fg * 8 + j]; }
    const float* xrow = x + (size_t)(m0 + rg * 2) * In;

    uint32_t a_st_off[2];
#pragma unroll
    for (int r = 0; r < 2; ++r) {
        uint32_t row = rg * 2 + r;
        a_st_off[r] = row * 128u + ((uint32_t)(fg * 16) ^ ((row & 7u) << 4));
    }

    // ---- producer mapping: W — thread covers half a B-row (64B)
    const int wrow = tid >> 1;          // 0..255
    const int wh = tid & 1;             // 0/1
    uint32_t w_st_off[4];
#pragma unroll
    for (int q = 0; q < 4; ++q)
        w_st_off[q] = (uint32_t)wrow * 128u +
                      (((uint32_t)(wh * 64 + q * 16)) ^ (((uint32_t)wrow & 7u) << 4));
    const __half* wbase = g_Wmat + (size_t)(n0 + wrow) * Fn + (size_t)wh * 32;

    // ---- consumer (ldmatrix) lane constants
    const int sub = lane >> 3, l7 = lane & 7;
    const uint32_t lxor = (uint32_t)l7 << 4;
    const uint32_t aR = (uint32_t)(wm * 64 + (sub & 1) * 8 + l7);
    const uint32_t aH = (uint32_t)((sub >> 1) * 16);
    const uint32_t bR = (uint32_t)(wn * 32 + (sub >> 1) * 8 + l7);
    const uint32_t bH = (uint32_t)((sub & 1) * 16);

    float c[4][4][4];
#pragma unroll
    for (int mt = 0; mt < 4; ++mt)
#pragma unroll
        for (int nt = 0; nt < 4; ++nt)
#pragma unroll
            for (int q = 0; q < 4; ++q) c[mt][nt][q] = 0.f;

#define PRODUCE(II)                                                              \
    {                                                                            \
        const int _i = (II);                                                     \
        const int _ss = _i & (STG - 1);                                          \
        const uint32_t _bb = sbase + SM_B0 + (uint32_t)_ss * B_BY;               \
        const __half* _ws = wbase + (size_t)_i * (On * Fn);                      \
        _Pragma("unroll")                                                        \
        for (int q = 0; q < 4; ++q)                                              \
            cp_async16(_bb + w_st_off[q], _ws + q * 8);                          \
        asm volatile("cp.async.commit_group;" ::: "memory");                     \
        const uint32_t _ab = sbase + (uint32_t)_ss * A_BY;                       \
        _Pragma("unroll")                                                        \
        for (int r = 0; r < 2; ++r) {                                            \
            const float xv = xrow[(size_t)r * In + _i];                          \
            uint32_t h[4];                                                       \
            _Pragma("unroll")                                                    \
            for (int j = 0; j < 4; ++j) {                                        \
                float s0 = __sinf(fmaf(wv[2 * j], xv, pv[2 * j]));               \
                float s1 = __sinf(fmaf(wv[2 * j + 1], xv, pv[2 * j + 1]));       \
                __half2 hh = __floats2half2_rn(s0, s1);                          \
                h[j] = *reinterpret_cast<uint32_t*>(&hh);                        \
            }                                                                    \
            sts128(_ab + a_st_off[r], h[0], h[1], h[2], h[3]);                   \
        }                                                                        \
    }

#define CONSUME(II)                                                              \
    {                                                                            \
        const int _s = (II) & (STG - 1);                                         \
        const uint32_t Ab = sbase + (uint32_t)_s * A_BY + aR * 128u;             \
        const uint32_t Bb = sbase + SM_B0 + (uint32_t)_s * B_BY + bR * 128u;     \
        _Pragma("unroll")                                                        \
        for (int ks = 0; ks < 4; ++ks) {                                         \
            const uint32_t kc = (uint32_t)(ks * 32);                             \
            uint32_t a[4][4];                                                    \
            _Pragma("unroll")                                                    \
            for (int mt = 0; mt < 4; ++mt)                                       \
                ldsm4(a[mt], Ab + (uint32_t)(mt * 16 * 128) + ((kc + aH) ^ lxor)); \
            uint32_t b[2][4];                                                    \
            _Pragma("unroll")                                                    \
            for (int np = 0; np < 2; ++np)                                       \
                ldsm4(b[np], Bb + (uint32_t)(np * 16 * 128) + ((kc + bH) ^ lxor)); \
            _Pragma("unroll")                                                    \
            for (int mt = 0; mt < 4; ++mt)                                       \
                _Pragma("unroll")                                                \
                for (int np = 0; np < 2; ++np) {                                 \
                    mma16816(c[mt][2 * np],     a[mt], &b[np][0]);               \
                    mma16816(c[mt][2 * np + 1], a[mt], &b[np][2]);               \
                }                                                                \
        }                                                                        \
    }

    // prologue: fill first pair (chunks 0,1)
    PRODUCE(0)
    PRODUCE(1)

    const bool early = (wid & 1) == 0;   // even warps produce first

#pragma unroll 1
    for (int t = 0; t < In / 2; ++t) {
        const int i0 = 2 * t;
        const bool more = (t < In / 2 - 1);
        // all outstanding cp.async groups are exactly chunks i0, i0+1
        asm volatile("cp.async.wait_group 0;" ::: "memory");
        __syncthreads();   // publish pair (cp.async + STS); guard stage reuse

        if (early) {
            if (more) PRODUCE(i0 + 2)
            CONSUME(i0)
            if (more) PRODUCE(i0 + 3)
            CONSUME(i0 + 1)
        } else {
            CONSUME(i0)
            if (more) PRODUCE(i0 + 2)
            CONSUME(i0 + 1)
            if (more) PRODUCE(i0 + 3)
        }
    }
#undef PRODUCE
#undef CONSUME

    // ================== epilogue ==================
    const int g = lane >> 2, t2 = lane & 3;
#pragma unroll
    for (int mt = 0; mt < 4; ++mt) {
#pragma unroll
        for (int nt = 0; nt < 4; ++nt) {
            const int row = m0 + wm * 64 + mt * 16 + g;
            const int col = n0 + wn * 32 + nt * 8 + t2 * 2;
            const float cr0 = g_corr[col], cr1 = g_corr[col + 1];
            float2 v0 = make_float2(c[mt][nt][0] + cr0, c[mt][nt][1] + cr1);
            float2 v1 = make_float2(c[mt][nt][2] + cr0, c[mt][nt][3] + cr1);
            *reinterpret_cast<float2*>(out + (size_t)row * On + col) = v0;
            *reinterpret_cast<float2*>(out + (size_t)(row + 8) * On + col) = v1;
        }
    }
}

// ---------------- harness entry ----------------
extern "C" void kernel_launch(void* const* d_in, const int* in_sizes, int n_in,
                              void* d_out, int out_size) {
    (void)in_sizes; (void)n_in; (void)out_size;
    const float* x      = (const float*)d_in[0];
    const float* freqs  = (const float*)d_in[1];
    const float* phases = (const float*)d_in[2];
    const float* beta   = (const float*)d_in[3];
    const float* lamb   = (const float*)d_in[4];
    const float* bias   = (const float*)d_in[5];
    float* out = (float*)d_out;

    cudaFuncSetAttribute(k_main, cudaFuncAttributeMaxDynamicSharedMemorySize, SMEM_TOTAL);

    k_fconst<<<1, 64>>>(freqs, phases);
    k_corr<<<1, 512>>>(beta, lamb, bias);
    k_W<<<512, 256>>>(beta, lamb);
    k_main<<<dim3(Bn / MT, On / NT), 512, SMEM_TOTAL>>>(x, freqs, phases, out);
}